// round 15
// baseline (speedup 1.0000x reference)
#include <cuda_runtime.h>
#include <cstdint>

// ---------------------------------------------------------------------------
// TernaryLinear, legacy-IMMA path (plain sm_100 toolchain: no tcgen05).
//   K1 (fused): per-row absmax int8 quant of x  AND  f32->int8 weight convert
//               (evict-first loads: single-use f32 streams kept out of L2)
//   K2: int8 GEMM mma.sync.m16n8k32, 4 warps @ 64x64, BK=64, 4-stage
//       cp.async, unconditional per-iteration commit, 2 CTA/SM.
//   R15 change: K-offset stagger -- co-resident CTAs start their K sweep 32
//       tiles apart ((bm^bn)&1), de-phasing barrier/LDSM bursts between the
//       two CTAs sharing an SM. Loop body & commit cadence byte-identical.
// ---------------------------------------------------------------------------

#define T_TOKENS 8192
#define KDIM     4096
#define ODIM     4096

#define BM 128
#define BN 128
#define BK 64              // int8 elems per k-tile
#define NSTAGE 4
#define KT (KDIM / BK)     // 64
#define A_BYTES (BM * BK)  // 8 KB
#define B_BYTES (BN * BK)  // 8 KB
#define STAGE_BYTES (A_BYTES + B_BYTES)    // 16 KB
#define DYN_SMEM (NSTAGE * STAGE_BYTES + 128)

#define W_BLOCKS ((ODIM * KDIM / 8) / 256)   // 8192 blocks, 2 float4/thread

__device__ __align__(128) int8_t g_xq[(size_t)T_TOKENS * KDIM];
__device__ __align__(128) int8_t g_wq[(size_t)ODIM * KDIM];
__device__ float g_ascale[T_TOKENS];

// --------------------------- helpers ---------------------------------------
__device__ __forceinline__ uint32_t cvta_s(const void* p) {
    return (uint32_t)__cvta_generic_to_shared(p);
}
__device__ __forceinline__ void cp_async16(uint32_t d, const void* s) {
    asm volatile("cp.async.cg.shared.global [%0], [%1], 16;\n" :: "r"(d), "l"(s));
}
__device__ __forceinline__ void cp_commit() {
    asm volatile("cp.async.commit_group;\n" ::: "memory");
}
template <int N> __device__ __forceinline__ void cp_wait() {
    asm volatile("cp.async.wait_group %0;\n" :: "n"(N) : "memory");
}
__device__ __forceinline__ void ldsm_x4(uint32_t* r, uint32_t addr) {
    asm volatile("ldmatrix.sync.aligned.m8n8.x4.shared.b16 {%0,%1,%2,%3}, [%4];"
                 : "=r"(r[0]), "=r"(r[1]), "=r"(r[2]), "=r"(r[3]) : "r"(addr));
}
__device__ __forceinline__ void mma16832(int* d, const uint32_t* a,
                                         uint32_t b0, uint32_t b1) {
    asm volatile(
        "mma.sync.aligned.m16n8k32.row.col.s32.s8.s8.s32 "
        "{%0,%1,%2,%3}, {%4,%5,%6,%7}, {%8,%9}, {%0,%1,%2,%3};\n"
        : "+r"(d[0]), "+r"(d[1]), "+r"(d[2]), "+r"(d[3])
        : "r"(a[0]), "r"(a[1]), "r"(a[2]), "r"(a[3]), "r"(b0), "r"(b1));
}
__device__ __forceinline__ signed char q8(float v, float inv) {
    return (signed char)(int)fminf(fmaxf(rintf(v * inv), -127.0f), 127.0f);
}
__device__ __forceinline__ float4 ldcs4(const float4* p) {
    return __ldcs(p);          // evict-first: single-use stream
}

// ---------------------------------------------------------------------------
// K1 fused: blocks [0, 8192) quantize x rows; blocks [8192, +8192) convert w
// (2 float4 per thread).
// ---------------------------------------------------------------------------
__global__ __launch_bounds__(256) void quant_fused_kernel(
    const float* __restrict__ x, const float* __restrict__ w) {
    if (blockIdx.x < T_TOKENS) {
        const int row = blockIdx.x;
        const float4* xr = reinterpret_cast<const float4*>(x + (size_t)row * KDIM);
        const int base = threadIdx.x << 2;

        float4 v[4];
        float m = 0.0f;
        #pragma unroll
        for (int j = 0; j < 4; j++) {
            v[j] = ldcs4(xr + base + j);
            m = fmaxf(m, fmaxf(fmaxf(fabsf(v[j].x), fabsf(v[j].y)),
                               fmaxf(fabsf(v[j].z), fabsf(v[j].w))));
        }
        #pragma unroll
        for (int o = 16; o; o >>= 1) m = fmaxf(m, __shfl_xor_sync(0xffffffffu, m, o));

        __shared__ float warpmax[8];
        __shared__ float s_inv;
        const int wid = threadIdx.x >> 5, lane = threadIdx.x & 31;
        if (lane == 0) warpmax[wid] = m;
        __syncthreads();
        if (threadIdx.x == 0) {
            float mm = warpmax[0];
            #pragma unroll
            for (int i = 1; i < 8; i++) mm = fmaxf(mm, warpmax[i]);
            float sc = fmaxf(mm, 1e-10f) / 127.0f;
            g_ascale[row] = sc;
            s_inv = 1.0f / sc;
        }
        __syncthreads();
        const float inv = s_inv;

        uint32_t p[4];
        #pragma unroll
        for (int j = 0; j < 4; j++) {
            char4 c = make_char4(q8(v[j].x, inv), q8(v[j].y, inv),
                                 q8(v[j].z, inv), q8(v[j].w, inv));
            p[j] = *reinterpret_cast<uint32_t*>(&c);
        }
        reinterpret_cast<uint4*>(g_xq + (size_t)row * KDIM)[threadIdx.x] =
            make_uint4(p[0], p[1], p[2], p[3]);
    } else {
        const size_t i = ((size_t)(blockIdx.x - T_TOKENS) * 256 + threadIdx.x) * 2;
        const float4* wp = reinterpret_cast<const float4*>(w);
        uint32_t p[2];
        #pragma unroll
        for (int j = 0; j < 2; j++) {
            const float4 v = ldcs4(wp + i + j);
            char4 c = make_char4((signed char)(int)v.x, (signed char)(int)v.y,
                                 (signed char)(int)v.z, (signed char)(int)v.w);
            p[j] = *reinterpret_cast<uint32_t*>(&c);
        }
        *reinterpret_cast<uint2*>(reinterpret_cast<char4*>(g_wq) + i) =
            make_uint2(p[0], p[1]);
    }
}

// ---------------------------------------------------------------------------
// K2: int8 GEMM. C[T,O] = xq[T,K] @ wq[O,K]^T
// smem rows 64B = 4 chunks of 16B; swizzle: phys_chunk = c ^ ((row>>1)&3)
// K sweep starts at kt0 per CTA parity; int32 accumulation is order-exact.
// ---------------------------------------------------------------------------
__global__ __launch_bounds__(128, 2)
void gemm_kernel(const float* __restrict__ wscale_p,
                 const float* __restrict__ bias,
                 float* __restrict__ out) {
    extern __shared__ int8_t smem_raw[];
    const uint32_t smem_u = (cvta_s(smem_raw) + 127u) & ~127u;

    const int tid  = threadIdx.x;
    const int lane = tid & 31;
    const int wid  = tid >> 5;
    const int wm   = wid & 1;
    const int wn   = wid >> 1;
    const int bm   = blockIdx.y;
    const int bn   = blockIdx.x;

    // K-offset stagger: half the CTAs start 32 tiles in (de-phases pairs)
    const int kt0 = ((bm ^ bn) & 1) << 5;

    const int8_t* Ag = g_xq + (size_t)bm * BM * KDIM;
    const int8_t* Bg = g_wq + (size_t)bn * BN * KDIM;

    auto load_tile = [&](int st, int kt) {
        const uint32_t sb = smem_u + st * STAGE_BYTES;
        const int koff = kt * BK;
        #pragma unroll
        for (int r = 0; r < 4; r++) {
            const int id  = tid + (r << 7);
            const int row = id >> 2;
            const int c   = id & 3;
            const uint32_t phys = (uint32_t)((c ^ ((row >> 1) & 3)) << 4);
            cp_async16(sb + row * BK + phys,
                       Ag + (size_t)row * KDIM + koff + (c << 4));
            cp_async16(sb + A_BYTES + row * BK + phys,
                       Bg + (size_t)row * KDIM + koff + (c << 4));
        }
    };

    uint32_t a_off[4];
    {
        const int m  = lane >> 3;
        const int rr = ((m & 1) << 3) + (lane & 7);
        const int cb = m >> 1;
        #pragma unroll
        for (int mi = 0; mi < 4; mi++) {
            const int row = wm * 64 + mi * 16 + rr;
            a_off[mi] = (uint32_t)(row * BK + ((cb ^ ((row >> 1) & 3)) << 4));
        }
    }
    uint32_t b_off[4];
    {
        const int m  = lane >> 3;
        const int cr = ((m >> 1) << 3) + (lane & 7);
        const int cb = m & 1;
        #pragma unroll
        for (int n2 = 0; n2 < 4; n2++) {
            const int col = wn * 64 + n2 * 16 + cr;
            b_off[n2] = (uint32_t)(A_BYTES + col * BK + ((cb ^ ((col >> 1) & 3)) << 4));
        }
    }

    int acc[4][8][4] = {};

    load_tile(0, kt0);
    cp_commit();
    load_tile(1, (kt0 + 1) & (KT - 1));
    cp_commit();
    load_tile(2, (kt0 + 2) & (KT - 1));
    cp_commit();

    for (int i = 0; i < KT; i++) {
        cp_wait<2>();
        __syncthreads();

        const uint32_t sb = smem_u + (uint32_t)((i & (NSTAGE - 1)) * STAGE_BYTES);

        uint32_t a[4][4], b[4][4];
        #pragma unroll
        for (int mi = 0; mi < 4; mi++) ldsm_x4(a[mi], sb + a_off[mi]);
        #pragma unroll
        for (int n2 = 0; n2 < 4; n2++)  ldsm_x4(b[n2], sb + b_off[n2]);

        const int nxt = i + 3;
        if (nxt < KT) load_tile(nxt & (NSTAGE - 1), (kt0 + nxt) & (KT - 1));
        cp_commit();                 // unconditional: keeps group cadence fixed

        #pragma unroll
        for (int mi = 0; mi < 4; mi++) {
            #pragma unroll
            for (int ni = 0; ni < 8; ni++) {
                const uint32_t* bb = b[ni >> 1];
                const int o = (ni & 1) << 1;
                mma16832(acc[mi][ni], a[mi], bb[o], bb[o + 1]);
            }
        }

        #pragma unroll
        for (int mi = 0; mi < 4; mi++) ldsm_x4(a[mi], sb + (a_off[mi] ^ 32u));
        #pragma unroll
        for (int n2 = 0; n2 < 4; n2++)  ldsm_x4(b[n2], sb + (b_off[n2] ^ 32u));
        #pragma unroll
        for (int mi = 0; mi < 4; mi++) {
            #pragma unroll
            for (int ni = 0; ni < 8; ni++) {
                const uint32_t* bb = b[ni >> 1];
                const int o = (ni & 1) << 1;
                mma16832(acc[mi][ni], a[mi], bb[o], bb[o + 1]);
            }
        }
    }

    // epilogue: y = acc * act_scale[row] * w_scale + bias[col]
    const float ws = __ldg(wscale_p);
    #pragma unroll
    for (int mi = 0; mi < 4; mi++) {
        const int r0 = bm * BM + wm * 64 + mi * 16 + (lane >> 2);
        const float s0 = g_ascale[r0] * ws;
        const float s1 = g_ascale[r0 + 8] * ws;
        #pragma unroll
        for (int ni = 0; ni < 8; ni++) {
            const int c = bn * BN + wn * 64 + ni * 8 + ((lane & 3) << 1);
            const float b0 = __ldg(bias + c);
            const float b1 = __ldg(bias + c + 1);
            float2 v0 = make_float2((float)acc[mi][ni][0] * s0 + b0,
                                    (float)acc[mi][ni][1] * s0 + b1);
            float2 v1 = make_float2((float)acc[mi][ni][2] * s1 + b0,
                                    (float)acc[mi][ni][3] * s1 + b1);
            *reinterpret_cast<float2*>(out + (size_t)r0 * ODIM + c)       = v0;
            *reinterpret_cast<float2*>(out + (size_t)(r0 + 8) * ODIM + c) = v1;
        }
    }
}

// ---------------------------------------------------------------------------
extern "C" void kernel_launch(void* const* d_in, const int* in_sizes, int n_in,
                              void* d_out, int out_size) {
    const float* x      = (const float*)d_in[0];   // [8192, 4096]
    const float* w_t    = (const float*)d_in[1];   // [4096, 4096]
    const float* wscale = (const float*)d_in[2];   // scalar
    const float* bias   = (const float*)d_in[3];   // [4096]
    float* out          = (float*)d_out;           // [8192, 4096]

    quant_fused_kernel<<<T_TOKENS + W_BLOCKS, 256>>>(x, w_t);

    cudaFuncSetAttribute(gemm_kernel, cudaFuncAttributeMaxDynamicSharedMemorySize,
                         DYN_SMEM);
    dim3 grid(ODIM / BN, T_TOKENS / BM);   // (32, 64)
    gemm_kernel<<<grid, 128, DYN_SMEM>>>(wscale, bias, out);
}

// round 16
// speedup vs baseline: 1.0102x; 1.0102x over previous
#include <cuda_runtime.h>
#include <cstdint>

// ---------------------------------------------------------------------------
// TernaryLinear, legacy-IMMA path (plain sm_100 toolchain: no tcgen05).
// Base = R12/R14 measured best (333.7us):
//   K1 (fused): per-row absmax int8 quant of x  AND  f32->int8 weight convert
//               (evict-first loads: single-use f32 streams kept out of L2)
//   K2: int8 GEMM mma.sync.m16n8k32, 4 warps @ 64x64, BK=64, 4-stage
//       cp.async, unconditional per-iteration commit, 2 CTA/SM
//       (tensor ~82% = issue-arbitration floor of fallback IMMA).
// R16 single-variable change: evict-first (__stcs) epilogue output stores --
//   out is 134MB write-once; keep xq/wq L2-resident for later-wave cp.asyncs.
//   Mainloop byte-identical to R14.
// ---------------------------------------------------------------------------

#define T_TOKENS 8192
#define KDIM     4096
#define ODIM     4096

#define BM 128
#define BN 128
#define BK 64              // int8 elems per k-tile
#define NSTAGE 4
#define KT (KDIM / BK)     // 64
#define A_BYTES (BM * BK)  // 8 KB
#define B_BYTES (BN * BK)  // 8 KB
#define STAGE_BYTES (A_BYTES + B_BYTES)    // 16 KB
#define DYN_SMEM (NSTAGE * STAGE_BYTES + 128)

#define W_BLOCKS ((ODIM * KDIM / 8) / 256)   // 8192 blocks, 2 float4/thread

__device__ __align__(128) int8_t g_xq[(size_t)T_TOKENS * KDIM];
__device__ __align__(128) int8_t g_wq[(size_t)ODIM * KDIM];
__device__ float g_ascale[T_TOKENS];

// --------------------------- helpers ---------------------------------------
__device__ __forceinline__ uint32_t cvta_s(const void* p) {
    return (uint32_t)__cvta_generic_to_shared(p);
}
__device__ __forceinline__ void cp_async16(uint32_t d, const void* s) {
    asm volatile("cp.async.cg.shared.global [%0], [%1], 16;\n" :: "r"(d), "l"(s));
}
__device__ __forceinline__ void cp_commit() {
    asm volatile("cp.async.commit_group;\n" ::: "memory");
}
template <int N> __device__ __forceinline__ void cp_wait() {
    asm volatile("cp.async.wait_group %0;\n" :: "n"(N) : "memory");
}
__device__ __forceinline__ void ldsm_x4(uint32_t* r, uint32_t addr) {
    asm volatile("ldmatrix.sync.aligned.m8n8.x4.shared.b16 {%0,%1,%2,%3}, [%4];"
                 : "=r"(r[0]), "=r"(r[1]), "=r"(r[2]), "=r"(r[3]) : "r"(addr));
}
__device__ __forceinline__ void mma16832(int* d, const uint32_t* a,
                                         uint32_t b0, uint32_t b1) {
    asm volatile(
        "mma.sync.aligned.m16n8k32.row.col.s32.s8.s8.s32 "
        "{%0,%1,%2,%3}, {%4,%5,%6,%7}, {%8,%9}, {%0,%1,%2,%3};\n"
        : "+r"(d[0]), "+r"(d[1]), "+r"(d[2]), "+r"(d[3])
        : "r"(a[0]), "r"(a[1]), "r"(a[2]), "r"(a[3]), "r"(b0), "r"(b1));
}
__device__ __forceinline__ signed char q8(float v, float inv) {
    return (signed char)(int)fminf(fmaxf(rintf(v * inv), -127.0f), 127.0f);
}
__device__ __forceinline__ float4 ldcs4(const float4* p) {
    return __ldcs(p);          // evict-first: single-use stream
}

// ---------------------------------------------------------------------------
// K1 fused: blocks [0, 8192) quantize x rows; blocks [8192, +8192) convert w
// (2 float4 per thread).
// ---------------------------------------------------------------------------
__global__ __launch_bounds__(256) void quant_fused_kernel(
    const float* __restrict__ x, const float* __restrict__ w) {
    if (blockIdx.x < T_TOKENS) {
        const int row = blockIdx.x;
        const float4* xr = reinterpret_cast<const float4*>(x + (size_t)row * KDIM);
        const int base = threadIdx.x << 2;

        float4 v[4];
        float m = 0.0f;
        #pragma unroll
        for (int j = 0; j < 4; j++) {
            v[j] = ldcs4(xr + base + j);
            m = fmaxf(m, fmaxf(fmaxf(fabsf(v[j].x), fabsf(v[j].y)),
                               fmaxf(fabsf(v[j].z), fabsf(v[j].w))));
        }
        #pragma unroll
        for (int o = 16; o; o >>= 1) m = fmaxf(m, __shfl_xor_sync(0xffffffffu, m, o));

        __shared__ float warpmax[8];
        __shared__ float s_inv;
        const int wid = threadIdx.x >> 5, lane = threadIdx.x & 31;
        if (lane == 0) warpmax[wid] = m;
        __syncthreads();
        if (threadIdx.x == 0) {
            float mm = warpmax[0];
            #pragma unroll
            for (int i = 1; i < 8; i++) mm = fmaxf(mm, warpmax[i]);
            float sc = fmaxf(mm, 1e-10f) / 127.0f;
            g_ascale[row] = sc;
            s_inv = 1.0f / sc;
        }
        __syncthreads();
        const float inv = s_inv;

        uint32_t p[4];
        #pragma unroll
        for (int j = 0; j < 4; j++) {
            char4 c = make_char4(q8(v[j].x, inv), q8(v[j].y, inv),
                                 q8(v[j].z, inv), q8(v[j].w, inv));
            p[j] = *reinterpret_cast<uint32_t*>(&c);
        }
        reinterpret_cast<uint4*>(g_xq + (size_t)row * KDIM)[threadIdx.x] =
            make_uint4(p[0], p[1], p[2], p[3]);
    } else {
        const size_t i = ((size_t)(blockIdx.x - T_TOKENS) * 256 + threadIdx.x) * 2;
        const float4* wp = reinterpret_cast<const float4*>(w);
        uint32_t p[2];
        #pragma unroll
        for (int j = 0; j < 2; j++) {
            const float4 v = ldcs4(wp + i + j);
            char4 c = make_char4((signed char)(int)v.x, (signed char)(int)v.y,
                                 (signed char)(int)v.z, (signed char)(int)v.w);
            p[j] = *reinterpret_cast<uint32_t*>(&c);
        }
        *reinterpret_cast<uint2*>(reinterpret_cast<char4*>(g_wq) + i) =
            make_uint2(p[0], p[1]);
    }
}

// ---------------------------------------------------------------------------
// K2: int8 GEMM. C[T,O] = xq[T,K] @ wq[O,K]^T     (R6/R12/R14 mainloop)
// smem rows 64B = 4 chunks of 16B; swizzle: phys_chunk = c ^ ((row>>1)&3)
// ---------------------------------------------------------------------------
__global__ __launch_bounds__(128, 2)
void gemm_kernel(const float* __restrict__ wscale_p,
                 const float* __restrict__ bias,
                 float* __restrict__ out) {
    extern __shared__ int8_t smem_raw[];
    const uint32_t smem_u = (cvta_s(smem_raw) + 127u) & ~127u;

    const int tid  = threadIdx.x;
    const int lane = tid & 31;
    const int wid  = tid >> 5;
    const int wm   = wid & 1;
    const int wn   = wid >> 1;
    const int bm   = blockIdx.y;
    const int bn   = blockIdx.x;

    const int8_t* Ag = g_xq + (size_t)bm * BM * KDIM;
    const int8_t* Bg = g_wq + (size_t)bn * BN * KDIM;

    auto load_tile = [&](int st, int kt) {
        const uint32_t sb = smem_u + st * STAGE_BYTES;
        const int koff = kt * BK;
        #pragma unroll
        for (int r = 0; r < 4; r++) {
            const int id  = tid + (r << 7);
            const int row = id >> 2;
            const int c   = id & 3;
            const uint32_t phys = (uint32_t)((c ^ ((row >> 1) & 3)) << 4);
            cp_async16(sb + row * BK + phys,
                       Ag + (size_t)row * KDIM + koff + (c << 4));
            cp_async16(sb + A_BYTES + row * BK + phys,
                       Bg + (size_t)row * KDIM + koff + (c << 4));
        }
    };

    uint32_t a_off[4];
    {
        const int m  = lane >> 3;
        const int rr = ((m & 1) << 3) + (lane & 7);
        const int cb = m >> 1;
        #pragma unroll
        for (int mi = 0; mi < 4; mi++) {
            const int row = wm * 64 + mi * 16 + rr;
            a_off[mi] = (uint32_t)(row * BK + ((cb ^ ((row >> 1) & 3)) << 4));
        }
    }
    uint32_t b_off[4];
    {
        const int m  = lane >> 3;
        const int cr = ((m >> 1) << 3) + (lane & 7);
        const int cb = m & 1;
        #pragma unroll
        for (int n2 = 0; n2 < 4; n2++) {
            const int col = wn * 64 + n2 * 16 + cr;
            b_off[n2] = (uint32_t)(A_BYTES + col * BK + ((cb ^ ((col >> 1) & 3)) << 4));
        }
    }

    int acc[4][8][4] = {};

    load_tile(0, 0); cp_commit();
    load_tile(1, 1); cp_commit();
    load_tile(2, 2); cp_commit();

    for (int kt = 0; kt < KT; kt++) {
        cp_wait<2>();
        __syncthreads();

        const uint32_t sb = smem_u + (uint32_t)((kt & (NSTAGE - 1)) * STAGE_BYTES);

        uint32_t a[4][4], b[4][4];
        #pragma unroll
        for (int mi = 0; mi < 4; mi++) ldsm_x4(a[mi], sb + a_off[mi]);
        #pragma unroll
        for (int n2 = 0; n2 < 4; n2++)  ldsm_x4(b[n2], sb + b_off[n2]);

        const int nxt = kt + 3;
        if (nxt < KT) load_tile(nxt & (NSTAGE - 1), nxt);
        cp_commit();                 // unconditional: keeps group cadence fixed

        #pragma unroll
        for (int mi = 0; mi < 4; mi++) {
            #pragma unroll
            for (int ni = 0; ni < 8; ni++) {
                const uint32_t* bb = b[ni >> 1];
                const int o = (ni & 1) << 1;
                mma16832(acc[mi][ni], a[mi], bb[o], bb[o + 1]);
            }
        }

        #pragma unroll
        for (int mi = 0; mi < 4; mi++) ldsm_x4(a[mi], sb + (a_off[mi] ^ 32u));
        #pragma unroll
        for (int n2 = 0; n2 < 4; n2++)  ldsm_x4(b[n2], sb + (b_off[n2] ^ 32u));
        #pragma unroll
        for (int mi = 0; mi < 4; mi++) {
            #pragma unroll
            for (int ni = 0; ni < 8; ni++) {
                const uint32_t* bb = b[ni >> 1];
                const int o = (ni & 1) << 1;
                mma16832(acc[mi][ni], a[mi], bb[o], bb[o + 1]);
            }
        }
    }

    // epilogue: y = acc * act_scale[row] * w_scale + bias[col]
    // R16: evict-first stores (write-once output; keep xq/wq resident in L2)
    const float ws = __ldg(wscale_p);
    #pragma unroll
    for (int mi = 0; mi < 4; mi++) {
        const int r0 = bm * BM + wm * 64 + mi * 16 + (lane >> 2);
        const float s0 = g_ascale[r0] * ws;
        const float s1 = g_ascale[r0 + 8] * ws;
        #pragma unroll
        for (int ni = 0; ni < 8; ni++) {
            const int c = bn * BN + wn * 64 + ni * 8 + ((lane & 3) << 1);
            const float b0 = __ldg(bias + c);
            const float b1 = __ldg(bias + c + 1);
            __stcs(reinterpret_cast<float2*>(out + (size_t)r0 * ODIM + c),
                   make_float2((float)acc[mi][ni][0] * s0 + b0,
                               (float)acc[mi][ni][1] * s0 + b1));
            __stcs(reinterpret_cast<float2*>(out + (size_t)(r0 + 8) * ODIM + c),
                   make_float2((float)acc[mi][ni][2] * s1 + b0,
                               (float)acc[mi][ni][3] * s1 + b1));
        }
    }
}

// ---------------------------------------------------------------------------
extern "C" void kernel_launch(void* const* d_in, const int* in_sizes, int n_in,
                              void* d_out, int out_size) {
    const float* x      = (const float*)d_in[0];   // [8192, 4096]
    const float* w_t    = (const float*)d_in[1];   // [4096, 4096]
    const float* wscale = (const float*)d_in[2];   // scalar
    const float* bias   = (const float*)d_in[3];   // [4096]
    float* out          = (float*)d_out;           // [8192, 4096]

    quant_fused_kernel<<<T_TOKENS + W_BLOCKS, 256>>>(x, w_t);

    cudaFuncSetAttribute(gemm_kernel, cudaFuncAttributeMaxDynamicSharedMemorySize,
                         DYN_SMEM);
    dim3 grid(ODIM / BN, T_TOKENS / BM);   // (32, 64)
    gemm_kernel<<<grid, 128, DYN_SMEM>>>(wscale, bias, out);
}

// round 17
// speedup vs baseline: 1.0115x; 1.0013x over previous
#include <cuda_runtime.h>
#include <cstdint>

// ---------------------------------------------------------------------------
// TernaryLinear, legacy-IMMA path (plain sm_100 toolchain: no tcgen05).
// Base = R16 measured best (332.2us):
//   K1 (fused): per-row absmax int8 quant of x  AND  f32->int8 weight convert
//               (evict-first loads: single-use f32 streams kept out of L2)
//   K2: int8 GEMM mma.sync.m16n8k32, 4 warps @ 64x64, BK=64, 4-stage
//       cp.async, unconditional per-iteration commit, 2 CTA/SM,
//       evict-first epilogue stores.
// R17 single-variable change: hoist bias loads in the epilogue (c depends
//   only on ni, not mi: 64 LDGs -> 16 per thread). Mainloop byte-identical.
// ---------------------------------------------------------------------------

#define T_TOKENS 8192
#define KDIM     4096
#define ODIM     4096

#define BM 128
#define BN 128
#define BK 64              // int8 elems per k-tile
#define NSTAGE 4
#define KT (KDIM / BK)     // 64
#define A_BYTES (BM * BK)  // 8 KB
#define B_BYTES (BN * BK)  // 8 KB
#define STAGE_BYTES (A_BYTES + B_BYTES)    // 16 KB
#define DYN_SMEM (NSTAGE * STAGE_BYTES + 128)

#define W_BLOCKS ((ODIM * KDIM / 8) / 256)   // 8192 blocks, 2 float4/thread

__device__ __align__(128) int8_t g_xq[(size_t)T_TOKENS * KDIM];
__device__ __align__(128) int8_t g_wq[(size_t)ODIM * KDIM];
__device__ float g_ascale[T_TOKENS];

// --------------------------- helpers ---------------------------------------
__device__ __forceinline__ uint32_t cvta_s(const void* p) {
    return (uint32_t)__cvta_generic_to_shared(p);
}
__device__ __forceinline__ void cp_async16(uint32_t d, const void* s) {
    asm volatile("cp.async.cg.shared.global [%0], [%1], 16;\n" :: "r"(d), "l"(s));
}
__device__ __forceinline__ void cp_commit() {
    asm volatile("cp.async.commit_group;\n" ::: "memory");
}
template <int N> __device__ __forceinline__ void cp_wait() {
    asm volatile("cp.async.wait_group %0;\n" :: "n"(N) : "memory");
}
__device__ __forceinline__ void ldsm_x4(uint32_t* r, uint32_t addr) {
    asm volatile("ldmatrix.sync.aligned.m8n8.x4.shared.b16 {%0,%1,%2,%3}, [%4];"
                 : "=r"(r[0]), "=r"(r[1]), "=r"(r[2]), "=r"(r[3]) : "r"(addr));
}
__device__ __forceinline__ void mma16832(int* d, const uint32_t* a,
                                         uint32_t b0, uint32_t b1) {
    asm volatile(
        "mma.sync.aligned.m16n8k32.row.col.s32.s8.s8.s32 "
        "{%0,%1,%2,%3}, {%4,%5,%6,%7}, {%8,%9}, {%0,%1,%2,%3};\n"
        : "+r"(d[0]), "+r"(d[1]), "+r"(d[2]), "+r"(d[3])
        : "r"(a[0]), "r"(a[1]), "r"(a[2]), "r"(a[3]), "r"(b0), "r"(b1));
}
__device__ __forceinline__ signed char q8(float v, float inv) {
    return (signed char)(int)fminf(fmaxf(rintf(v * inv), -127.0f), 127.0f);
}
__device__ __forceinline__ float4 ldcs4(const float4* p) {
    return __ldcs(p);          // evict-first: single-use stream
}

// ---------------------------------------------------------------------------
// K1 fused: blocks [0, 8192) quantize x rows; blocks [8192, +8192) convert w
// (2 float4 per thread).
// ---------------------------------------------------------------------------
__global__ __launch_bounds__(256) void quant_fused_kernel(
    const float* __restrict__ x, const float* __restrict__ w) {
    if (blockIdx.x < T_TOKENS) {
        const int row = blockIdx.x;
        const float4* xr = reinterpret_cast<const float4*>(x + (size_t)row * KDIM);
        const int base = threadIdx.x << 2;

        float4 v[4];
        float m = 0.0f;
        #pragma unroll
        for (int j = 0; j < 4; j++) {
            v[j] = ldcs4(xr + base + j);
            m = fmaxf(m, fmaxf(fmaxf(fabsf(v[j].x), fabsf(v[j].y)),
                               fmaxf(fabsf(v[j].z), fabsf(v[j].w))));
        }
        #pragma unroll
        for (int o = 16; o; o >>= 1) m = fmaxf(m, __shfl_xor_sync(0xffffffffu, m, o));

        __shared__ float warpmax[8];
        __shared__ float s_inv;
        const int wid = threadIdx.x >> 5, lane = threadIdx.x & 31;
        if (lane == 0) warpmax[wid] = m;
        __syncthreads();
        if (threadIdx.x == 0) {
            float mm = warpmax[0];
            #pragma unroll
            for (int i = 1; i < 8; i++) mm = fmaxf(mm, warpmax[i]);
            float sc = fmaxf(mm, 1e-10f) / 127.0f;
            g_ascale[row] = sc;
            s_inv = 1.0f / sc;
        }
        __syncthreads();
        const float inv = s_inv;

        uint32_t p[4];
        #pragma unroll
        for (int j = 0; j < 4; j++) {
            char4 c = make_char4(q8(v[j].x, inv), q8(v[j].y, inv),
                                 q8(v[j].z, inv), q8(v[j].w, inv));
            p[j] = *reinterpret_cast<uint32_t*>(&c);
        }
        reinterpret_cast<uint4*>(g_xq + (size_t)row * KDIM)[threadIdx.x] =
            make_uint4(p[0], p[1], p[2], p[3]);
    } else {
        const size_t i = ((size_t)(blockIdx.x - T_TOKENS) * 256 + threadIdx.x) * 2;
        const float4* wp = reinterpret_cast<const float4*>(w);
        uint32_t p[2];
        #pragma unroll
        for (int j = 0; j < 2; j++) {
            const float4 v = ldcs4(wp + i + j);
            char4 c = make_char4((signed char)(int)v.x, (signed char)(int)v.y,
                                 (signed char)(int)v.z, (signed char)(int)v.w);
            p[j] = *reinterpret_cast<uint32_t*>(&c);
        }
        *reinterpret_cast<uint2*>(reinterpret_cast<char4*>(g_wq) + i) =
            make_uint2(p[0], p[1]);
    }
}

// ---------------------------------------------------------------------------
// K2: int8 GEMM. C[T,O] = xq[T,K] @ wq[O,K]^T     (R6/R12/R14/R16 mainloop)
// smem rows 64B = 4 chunks of 16B; swizzle: phys_chunk = c ^ ((row>>1)&3)
// ---------------------------------------------------------------------------
__global__ __launch_bounds__(128, 2)
void gemm_kernel(const float* __restrict__ wscale_p,
                 const float* __restrict__ bias,
                 float* __restrict__ out) {
    extern __shared__ int8_t smem_raw[];
    const uint32_t smem_u = (cvta_s(smem_raw) + 127u) & ~127u;

    const int tid  = threadIdx.x;
    const int lane = tid & 31;
    const int wid  = tid >> 5;
    const int wm   = wid & 1;
    const int wn   = wid >> 1;
    const int bm   = blockIdx.y;
    const int bn   = blockIdx.x;

    const int8_t* Ag = g_xq + (size_t)bm * BM * KDIM;
    const int8_t* Bg = g_wq + (size_t)bn * BN * KDIM;

    auto load_tile = [&](int st, int kt) {
        const uint32_t sb = smem_u + st * STAGE_BYTES;
        const int koff = kt * BK;
        #pragma unroll
        for (int r = 0; r < 4; r++) {
            const int id  = tid + (r << 7);
            const int row = id >> 2;
            const int c   = id & 3;
            const uint32_t phys = (uint32_t)((c ^ ((row >> 1) & 3)) << 4);
            cp_async16(sb + row * BK + phys,
                       Ag + (size_t)row * KDIM + koff + (c << 4));
            cp_async16(sb + A_BYTES + row * BK + phys,
                       Bg + (size_t)row * KDIM + koff + (c << 4));
        }
    };

    uint32_t a_off[4];
    {
        const int m  = lane >> 3;
        const int rr = ((m & 1) << 3) + (lane & 7);
        const int cb = m >> 1;
        #pragma unroll
        for (int mi = 0; mi < 4; mi++) {
            const int row = wm * 64 + mi * 16 + rr;
            a_off[mi] = (uint32_t)(row * BK + ((cb ^ ((row >> 1) & 3)) << 4));
        }
    }
    uint32_t b_off[4];
    {
        const int m  = lane >> 3;
        const int cr = ((m >> 1) << 3) + (lane & 7);
        const int cb = m & 1;
        #pragma unroll
        for (int n2 = 0; n2 < 4; n2++) {
            const int col = wn * 64 + n2 * 16 + cr;
            b_off[n2] = (uint32_t)(A_BYTES + col * BK + ((cb ^ ((col >> 1) & 3)) << 4));
        }
    }

    int acc[4][8][4] = {};

    load_tile(0, 0); cp_commit();
    load_tile(1, 1); cp_commit();
    load_tile(2, 2); cp_commit();

    for (int kt = 0; kt < KT; kt++) {
        cp_wait<2>();
        __syncthreads();

        const uint32_t sb = smem_u + (uint32_t)((kt & (NSTAGE - 1)) * STAGE_BYTES);

        uint32_t a[4][4], b[4][4];
        #pragma unroll
        for (int mi = 0; mi < 4; mi++) ldsm_x4(a[mi], sb + a_off[mi]);
        #pragma unroll
        for (int n2 = 0; n2 < 4; n2++)  ldsm_x4(b[n2], sb + b_off[n2]);

        const int nxt = kt + 3;
        if (nxt < KT) load_tile(nxt & (NSTAGE - 1), nxt);
        cp_commit();                 // unconditional: keeps group cadence fixed

        #pragma unroll
        for (int mi = 0; mi < 4; mi++) {
            #pragma unroll
            for (int ni = 0; ni < 8; ni++) {
                const uint32_t* bb = b[ni >> 1];
                const int o = (ni & 1) << 1;
                mma16832(acc[mi][ni], a[mi], bb[o], bb[o + 1]);
            }
        }

        #pragma unroll
        for (int mi = 0; mi < 4; mi++) ldsm_x4(a[mi], sb + (a_off[mi] ^ 32u));
        #pragma unroll
        for (int n2 = 0; n2 < 4; n2++)  ldsm_x4(b[n2], sb + (b_off[n2] ^ 32u));
        #pragma unroll
        for (int mi = 0; mi < 4; mi++) {
            #pragma unroll
            for (int ni = 0; ni < 8; ni++) {
                const uint32_t* bb = b[ni >> 1];
                const int o = (ni & 1) << 1;
                mma16832(acc[mi][ni], a[mi], bb[o], bb[o + 1]);
            }
        }
    }

    // epilogue: y = acc * act_scale[row] * w_scale + bias[col]
    // R17: bias loads hoisted (c depends only on ni); evict-first stores.
    const float ws = __ldg(wscale_p);
    float2 bv[8];
    #pragma unroll
    for (int ni = 0; ni < 8; ni++) {
        const int c = bn * BN + wn * 64 + ni * 8 + ((lane & 3) << 1);
        bv[ni] = make_float2(__ldg(bias + c), __ldg(bias + c + 1));
    }
    #pragma unroll
    for (int mi = 0; mi < 4; mi++) {
        const int r0 = bm * BM + wm * 64 + mi * 16 + (lane >> 2);
        const float s0 = g_ascale[r0] * ws;
        const float s1 = g_ascale[r0 + 8] * ws;
        #pragma unroll
        for (int ni = 0; ni < 8; ni++) {
            const int c = bn * BN + wn * 64 + ni * 8 + ((lane & 3) << 1);
            __stcs(reinterpret_cast<float2*>(out + (size_t)r0 * ODIM + c),
                   make_float2((float)acc[mi][ni][0] * s0 + bv[ni].x,
                               (float)acc[mi][ni][1] * s0 + bv[ni].y));
            __stcs(reinterpret_cast<float2*>(out + (size_t)(r0 + 8) * ODIM + c),
                   make_float2((float)acc[mi][ni][2] * s1 + bv[ni].x,
                               (float)acc[mi][ni][3] * s1 + bv[ni].y));
        }
    }
}

// ---------------------------------------------------------------------------
extern "C" void kernel_launch(void* const* d_in, const int* in_sizes, int n_in,
                              void* d_out, int out_size) {
    const float* x      = (const float*)d_in[0];   // [8192, 4096]
    const float* w_t    = (const float*)d_in[1];   // [4096, 4096]
    const float* wscale = (const float*)d_in[2];   // scalar
    const float* bias   = (const float*)d_in[3];   // [4096]
    float* out          = (float*)d_out;           // [8192, 4096]

    quant_fused_kernel<<<T_TOKENS + W_BLOCKS, 256>>>(x, w_t);

    cudaFuncSetAttribute(gemm_kernel, cudaFuncAttributeMaxDynamicSharedMemorySize,
                         DYN_SMEM);
    dim3 grid(ODIM / BN, T_TOKENS / BM);   // (32, 64)
    gemm_kernel<<<grid, 128, DYN_SMEM>>>(wscale, bias, out);
}